// round 8
// baseline (speedup 1.0000x reference)
#include <cuda_runtime.h>
#include <mma.h>
#include <cuda_fp16.h>
#include <cstdint>
#include <cmath>

using namespace nvcuda;

// ============================ problem constants ============================
constexpr int NE     = 8;
constexpr int DMODEL = 1024;
constexpr int FF     = 2048;
constexpr int NTOK   = 8192;   // 4*2048
constexpr int CAP    = 8192;   // per-expert worst-case rows

// ============================ scratch (module-load) ========================
__device__ __half g_xh [(size_t)NTOK * DMODEL];        // fp16 x              (16 MB)
__device__ __half g_W1h[(size_t)NE * DMODEL * FF];     // fp16 W1             (32 MB)
__device__ __half g_W2h[(size_t)NE * FF * DMODEL];     // fp16 W2             (32 MB)
__device__ __half g_Hh [(size_t)NE * CAP * FF];        // fp16 hidden         (256 MB)
__device__ float  g_Y  [(size_t)NE * CAP * DMODEL];    // expert outputs fp32 (256 MB)
__device__ int    g_tok  [NE * CAP];
__device__ int    g_cnt  [NE];                         // zero-init; reset by combine tail
__device__ int    g_oslot[NTOK * 2];
__device__ float  g_ogate[NTOK * 2];

// ============================ helpers ======================================
__device__ __forceinline__ uint32_t smem_u32(const void* p) {
    uint32_t a;
    asm("{ .reg .u64 t; cvta.to.shared.u64 t, %1; cvt.u32.u64 %0, t; }" : "=r"(a) : "l"(p));
    return a;
}
#define CP_ASYNC16(dst, src) \
    asm volatile("cp.async.cg.shared.global [%0], [%1], 16;" :: "r"(dst), "l"(src) : "memory")
#define CP_COMMIT()  asm volatile("cp.async.commit_group;" ::: "memory")

__device__ __forceinline__ float gelu_exact(float v) {
    return 0.5f * v * (1.0f + erff(v * 0.70710678118654752f));
}

// ============================ GEMM config ==================================
constexpr int BM = 128;
constexpr int BN = 128;
constexpr int BK = 64;
constexpr int PIPE = 2;
constexpr int THREADS = 256;
constexpr int ASTR = 72;                    // A smem stride (halves) = 144B
constexpr int BSTR = 136;                   // B smem stride (halves) = 272B
constexpr int A_HV = BM * ASTR;             // 9216 halves
constexpr int B_HV = BK * BSTR;             // 8704 halves
constexpr int ST_HV = A_HV + B_HV;          // 17920 halves = 35840 B per stage
constexpr int SMEM_BYTES = PIPE * ST_HV * 2;   // 71680 B  (2 CTAs/SM fit)

using FragC = wmma::fragment<wmma::accumulator, 16, 16, 16, float>;

// Mainloop: 128x128x64 CTA tile, double-buffered cp.async, wmma m16n16k16.
// Warp tile 64x32 (8 warps). arow/brow pre-offset to this thread's columns.
template <int NSTG, int LDB>
__device__ __forceinline__ void gemm_core(const __half* arow, const __half* brow,
                                          __half* sh, int tid, FragC (&cf)[4][2]) {
    uint32_t smb = smem_u32(sh);
    const int ar = tid >> 1;            // 0..127 (A row)
    const int ac = (tid & 1) * 32;      // halves
    const int br = tid >> 2;            // 0..63  (B row)
    const int bc = (tid & 3) * 32;      // halves
    const uint32_t a_dst = smb + (uint32_t)(ar * ASTR + ac) * 2u;
    const uint32_t b_dst = smb + (uint32_t)(A_HV + br * BSTR + bc) * 2u;

    auto load_stage = [&](int s) {
        uint32_t so = (uint32_t)((s & 1) * ST_HV) * 2u;
        const __half* as = arow + s * BK;
        uint32_t ad = a_dst + so;
#pragma unroll
        for (int i = 0; i < 4; i++) CP_ASYNC16(ad + i * 16, as + i * 8);
        const __half* bs = brow + (size_t)s * (BK * LDB);
        uint32_t bd = b_dst + so;
#pragma unroll
        for (int i = 0; i < 4; i++) CP_ASYNC16(bd + i * 16, bs + i * 8);
    };

    const int wid = tid >> 5;
    const int wm  = wid >> 2;   // 0..1 (64-row slab)
    const int wn  = wid & 3;    // 0..3 (32-col slab)

#pragma unroll
    for (int i = 0; i < 4; i++)
#pragma unroll
        for (int j = 0; j < 2; j++) wmma::fill_fragment(cf[i][j], 0.f);

    load_stage(0);
    CP_COMMIT();

    for (int s = 0; s < NSTG; s++) {
        if (s + 1 < NSTG) {
            load_stage(s + 1);
            CP_COMMIT();
            asm volatile("cp.async.wait_group 1;" ::: "memory");
        } else {
            asm volatile("cp.async.wait_group 0;" ::: "memory");
        }
        __syncthreads();

        const __half* A = sh + (s & 1) * ST_HV;
        const __half* B = A + A_HV;
        wmma::fragment<wmma::matrix_a, 16, 16, 16, __half, wmma::row_major> af;
        wmma::fragment<wmma::matrix_b, 16, 16, 16, __half, wmma::row_major> bf[2];
#pragma unroll
        for (int kk = 0; kk < BK; kk += 16) {
#pragma unroll
            for (int j = 0; j < 2; j++)
                wmma::load_matrix_sync(bf[j], B + kk * BSTR + wn * 32 + j * 16, BSTR);
#pragma unroll
            for (int i = 0; i < 4; i++) {
                wmma::load_matrix_sync(af, A + (wm * 64 + i * 16) * ASTR + kk, ASTR);
#pragma unroll
                for (int j = 0; j < 2; j++) wmma::mma_sync(cf[i][j], af, bf[j], cf[i][j]);
            }
        }
        __syncthreads();   // protect buffer (s+1)&1 reuse on next-next iteration
    }
}

// ============================ GEMM1: H = gelu(X W1 + b1) ===================
__global__ __launch_bounds__(THREADS, 2) void ffn1_tc(const float* __restrict__ b1) {
    int e = blockIdx.z;
    int cnt = g_cnt[e];
    int m0 = blockIdx.y * BM;
    if (m0 >= cnt) return;
    int n0 = blockIdx.x * BN;

    extern __shared__ __align__(16) char smem[];
    __half* sh = (__half*)smem;
    int tid = threadIdx.x, wid = tid >> 5, lane = tid & 31;
    int wm = wid >> 2, wn = wid & 3;

    // A gather: clamp inactive rows to a valid slot (masked in epilogue)
    int ar = tid >> 1, ac = (tid & 1) * 32;
    int gr = m0 + ar;
    int tok = g_tok[e * CAP + (gr < cnt ? gr : cnt - 1)];
    const __half* arow = g_xh + (size_t)tok * DMODEL + ac;

    int br = tid >> 2, bc = (tid & 3) * 32;
    const __half* brow = g_W1h + ((size_t)e * DMODEL + br) * FF + n0 + bc;

    FragC cf[4][2];
    gemm_core<DMODEL / BK, FF>(arow, brow, sh, tid, cf);

    // epilogue: bias + exact GELU -> fp16 H (stage each 16x16 frag via smem)
    float* cw = (float*)smem + wid * 320;   // 16 x 20 fp32 per warp
    const float* bb = b1 + (size_t)e * FF;
#pragma unroll
    for (int i = 0; i < 4; i++) {
#pragma unroll
        for (int j = 0; j < 2; j++) {
            wmma::store_matrix_sync(cw, cf[i][j], 20, wmma::mem_row_major);
            __syncwarp();
            int gmb = m0 + wm * 64 + i * 16;
            int gnb = n0 + wn * 32 + j * 16;
#pragma unroll
            for (int q = 0; q < 4; q++) {
                int idx = lane * 4 + q;          // 0..127 pairs
                int r = idx >> 3, c = (idx & 7) * 2;
                int gm = gmb + r;
                if (gm < cnt) {
                    int gn = gnb + c;
                    float v0 = gelu_exact(cw[r * 20 + c]     + bb[gn]);
                    float v1 = gelu_exact(cw[r * 20 + c + 1] + bb[gn + 1]);
                    *(__half2*)(g_Hh + ((size_t)e * CAP + gm) * FF + gn) =
                        __floats2half2_rn(v0, v1);
                }
            }
            __syncwarp();
        }
    }
}

// ============================ GEMM2: Y = H W2 + b2 =========================
__global__ __launch_bounds__(THREADS, 2) void ffn2_tc(const float* __restrict__ b2) {
    int e = blockIdx.z;
    int cnt = g_cnt[e];
    int m0 = blockIdx.y * BM;
    if (m0 >= cnt) return;
    int n0 = blockIdx.x * BN;

    extern __shared__ __align__(16) char smem[];
    __half* sh = (__half*)smem;
    int tid = threadIdx.x, wid = tid >> 5, lane = tid & 31;
    int wm = wid >> 2, wn = wid & 3;

    int ar = tid >> 1, ac = (tid & 1) * 32;
    const __half* arow = g_Hh + ((size_t)e * CAP + m0 + ar) * FF + ac;  // in-bounds, finite

    int br = tid >> 2, bc = (tid & 3) * 32;
    const __half* brow = g_W2h + ((size_t)e * FF + br) * DMODEL + n0 + bc;

    FragC cf[4][2];
    gemm_core<FF / BK, DMODEL>(arow, brow, sh, tid, cf);

    float* cw = (float*)smem + wid * 320;
    const float* bb = b2 + (size_t)e * DMODEL;
#pragma unroll
    for (int i = 0; i < 4; i++) {
#pragma unroll
        for (int j = 0; j < 2; j++) {
            wmma::store_matrix_sync(cw, cf[i][j], 20, wmma::mem_row_major);
            __syncwarp();
            int gmb = m0 + wm * 64 + i * 16;
            int gnb = n0 + wn * 32 + j * 16;
#pragma unroll
            for (int q = 0; q < 4; q++) {
                int idx = lane * 4 + q;
                int r = idx >> 3, c = (idx & 7) * 2;
                int gm = gmb + r;
                if (gm < cnt) {
                    int gn = gnb + c;
                    float2 v;
                    v.x = cw[r * 20 + c]     + bb[gn];
                    v.y = cw[r * 20 + c + 1] + bb[gn + 1];
                    *(float2*)(g_Y + ((size_t)e * CAP + gm) * DMODEL + gn) = v;
                }
            }
            __syncwarp();
        }
    }
}

// ============================ combine + counter reset ======================
__global__ void combine_kernel(float* __restrict__ out) {
    int i = blockIdx.x * blockDim.x + threadIdx.x;   // over NTOK * DMODEL/4
    if (i < NTOK * (DMODEL / 4)) {
        int n  = i >> 8;            // DMODEL/4 == 256
        int c4 = i & 255;
        int   s1 = g_oslot[n * 2 + 0], s2 = g_oslot[n * 2 + 1];
        float g1 = g_ogate[n * 2 + 0], g2 = g_ogate[n * 2 + 1];
        float4 y1 = reinterpret_cast<const float4*>(g_Y + (size_t)s1 * DMODEL)[c4];
        float4 y2 = reinterpret_cast<const float4*>(g_Y + (size_t)s2 * DMODEL)[c4];
        float4 o;
        o.x = g1 * y1.x + g2 * y2.x;
        o.y = g1 * y1.y + g2 * y2.y;
        o.z = g1 * y1.z + g2 * y2.z;
        o.w = g1 * y1.w + g2 * y2.w;
        reinterpret_cast<float4*>(out)[i] = o;
    }
    if (blockIdx.x == 0 && threadIdx.x < NE) g_cnt[threadIdx.x] = 0;  // ready next call
}

// ============================ fp32 -> fp16 conversion ======================
__global__ void conv2(const float* __restrict__ s1, __half* __restrict__ d1, int n1,
                      const float* __restrict__ s2, __half* __restrict__ d2, int n2) {
    int i = blockIdx.x * blockDim.x + threadIdx.x;   // float4 units
    const float* s; __half* d; int k;
    if (i < n1)            { s = s1; d = d1; k = i; }
    else if (i < n1 + n2)  { s = s2; d = d2; k = i - n1; }
    else return;
    float4 v = reinterpret_cast<const float4*>(s)[k];
    __half2* dp = reinterpret_cast<__half2*>(d);
    dp[k * 2]     = __floats2half2_rn(v.x, v.y);
    dp[k * 2 + 1] = __floats2half2_rn(v.z, v.w);
}

// ============================ router =======================================
__global__ void router_kernel(const float* __restrict__ x, const float* __restrict__ Wr) {
    int warp = (blockIdx.x * blockDim.x + threadIdx.x) >> 5;
    int lane = threadIdx.x & 31;
    if (warp >= NTOK) return;

    const float* xr = x + (size_t)warp * DMODEL;
    float acc[NE];
#pragma unroll
    for (int e = 0; e < NE; e++) acc[e] = 0.f;
#pragma unroll 4
    for (int i = 0; i < DMODEL / 32; i++) {
        int d = i * 32 + lane;
        float xv = xr[d];
#pragma unroll
        for (int e = 0; e < NE; e++) acc[e] += xv * Wr[e * DMODEL + d];
    }
#pragma unroll
    for (int e = 0; e < NE; e++)
#pragma unroll
        for (int o = 16; o > 0; o >>= 1)
            acc[e] += __shfl_xor_sync(0xffffffffu, acc[e], o);

    if (lane == 0) {
        float m = acc[0];
#pragma unroll
        for (int e = 1; e < NE; e++) m = fmaxf(m, acc[e]);
        float p[NE];
#pragma unroll
        for (int e = 0; e < NE; e++) p[e] = expf(acc[e] - m);
        int i1 = 0;
#pragma unroll
        for (int e = 1; e < NE; e++) if (p[e] > p[i1]) i1 = e;
        int i2 = (i1 == 0) ? 1 : 0;
#pragma unroll
        for (int e = 0; e < NE; e++) {
            if (e == i1) continue;
            if (p[e] > p[i2]) i2 = e;
        }
        float g1 = p[i1], g2 = p[i2];
        float inv = 1.f / (g1 + g2);
        g1 *= inv; g2 *= inv;

        int pos1 = atomicAdd(&g_cnt[i1], 1);
        g_tok[i1 * CAP + pos1] = warp;
        g_oslot[warp * 2 + 0] = i1 * CAP + pos1;
        g_ogate[warp * 2 + 0] = g1;

        int pos2 = atomicAdd(&g_cnt[i2], 1);
        g_tok[i2 * CAP + pos2] = warp;
        g_oslot[warp * 2 + 1] = i2 * CAP + pos2;
        g_ogate[warp * 2 + 1] = g2;
    }
}

// ============================ launch =======================================
extern "C" void kernel_launch(void* const* d_in, const int* in_sizes, int n_in,
                              void* d_out, int out_size) {
    const float* x  = (const float*)d_in[0];
    const float* Wr = (const float*)d_in[1];
    const float* W1 = (const float*)d_in[2];
    const float* b1 = (const float*)d_in[3];
    const float* W2 = (const float*)d_in[4];
    const float* b2 = (const float*)d_in[5];
    float* out = (float*)d_out;

    cudaFuncSetAttribute(ffn1_tc, cudaFuncAttributeMaxDynamicSharedMemorySize, SMEM_BYTES);
    cudaFuncSetAttribute(ffn2_tc, cudaFuncAttributeMaxDynamicSharedMemorySize, SMEM_BYTES);

    __half *pXh = nullptr, *pW1h = nullptr, *pW2h = nullptr;
    cudaGetSymbolAddress((void**)&pXh,  g_xh);
    cudaGetSymbolAddress((void**)&pW1h, g_W1h);
    cudaGetSymbolAddress((void**)&pW2h, g_W2h);

    int nx4 = NTOK * DMODEL / 4;             // 2M
    int nw4 = NE * DMODEL * FF / 4;          // 4M

    router_kernel<<<(NTOK * 32) / 256, 256>>>(x, Wr);                     // 1
    conv2<<<(nx4 + nw4 + 255) / 256, 256>>>(x, pXh, nx4, W1, pW1h, nw4);  // 2
    conv2<<<(nw4 + 255) / 256, 256>>>(W2, pW2h, nw4, W2, pW2h, 0);        // 3
    ffn1_tc<<<dim3(FF / BN, CAP / BM, NE), THREADS, SMEM_BYTES>>>(b1);    // 4
    ffn2_tc<<<dim3(DMODEL / BN, CAP / BM, NE), THREADS, SMEM_BYTES>>>(b2);// 5
    combine_kernel<<<(NTOK * DMODEL / 4 + 255) / 256, 256>>>(out);        // 6
}

// round 9
// speedup vs baseline: 1.2394x; 1.2394x over previous
#include <cuda_runtime.h>
#include <cuda_fp16.h>
#include <cstdint>
#include <cmath>

// ============================ problem constants ============================
constexpr int NE     = 8;
constexpr int DMODEL = 1024;
constexpr int FF     = 2048;
constexpr int NTOK   = 8192;   // 4*2048
constexpr int CAP    = 8192;   // per-expert worst-case rows

// ============================ scratch (module-load) ========================
__device__ __half g_xh [(size_t)NTOK * DMODEL];        // fp16 x              (16 MB)
__device__ __half g_W1h[(size_t)NE * DMODEL * FF];     // fp16 W1             (32 MB)
__device__ __half g_W2h[(size_t)NE * FF * DMODEL];     // fp16 W2             (32 MB)
__device__ __half g_Hh [(size_t)NE * CAP * FF];        // fp16 hidden         (256 MB)
__device__ float  g_Y  [(size_t)NE * CAP * DMODEL];    // expert outputs fp32 (256 MB)
__device__ int    g_tok  [NE * CAP];
__device__ int    g_cnt  [NE];                         // zero-init; reset by combine tail
__device__ int    g_oslot[NTOK * 2];
__device__ float  g_ogate[NTOK * 2];

// ============================ helpers ======================================
__device__ __forceinline__ uint32_t smem_u32(const void* p) {
    uint32_t a;
    asm("{ .reg .u64 t; cvta.to.shared.u64 t, %1; cvt.u32.u64 %0, t; }" : "=r"(a) : "l"(p));
    return a;
}
#define CP_ASYNC16(dst, src) \
    asm volatile("cp.async.cg.shared.global [%0], [%1], 16;" :: "r"(dst), "l"(src) : "memory")
#define CP_COMMIT()  asm volatile("cp.async.commit_group;" ::: "memory")

#define LDSM_X4(r0, r1, r2, r3, a) \
    asm volatile("ldmatrix.sync.aligned.m8n8.x4.shared.b16 {%0,%1,%2,%3}, [%4];" \
                 : "=r"(r0), "=r"(r1), "=r"(r2), "=r"(r3) : "r"(a))
#define LDSM_X4T(r0, r1, r2, r3, a) \
    asm volatile("ldmatrix.sync.aligned.m8n8.x4.trans.shared.b16 {%0,%1,%2,%3}, [%4];" \
                 : "=r"(r0), "=r"(r1), "=r"(r2), "=r"(r3) : "r"(a))
#define MMA16816(c, a, b0_, b1_) \
    asm volatile("mma.sync.aligned.m16n8k16.row.col.f32.f16.f16.f32 " \
                 "{%0,%1,%2,%3}, {%4,%5,%6,%7}, {%8,%9}, {%0,%1,%2,%3};" \
                 : "+f"((c)[0]), "+f"((c)[1]), "+f"((c)[2]), "+f"((c)[3]) \
                 : "r"((a)[0]), "r"((a)[1]), "r"((a)[2]), "r"((a)[3]), \
                   "r"(b0_), "r"(b1_))

__device__ __forceinline__ float gelu_exact(float v) {
    return 0.5f * v * (1.0f + erff(v * 0.70710678118654752f));
}

// ============================ GEMM config ==================================
constexpr int BM = 128;
constexpr int BN = 128;
constexpr int BK = 32;
constexpr int PIPE = 3;
constexpr int THREADS = 256;
constexpr int ASTR = 40;                     // halves: 80B row  (LDSM conflict-free)
constexpr int BSTR = 136;                    // halves: 272B row (LDSM conflict-free)
constexpr int A_BY = BM * ASTR * 2;          // 10240 B
constexpr int B_BY = BK * BSTR * 2;          // 8704 B
constexpr int ST_BY = A_BY + B_BY;           // 18944 B per stage
constexpr int SMEM_BYTES = PIPE * ST_BY;     // 56832 B

// Mainloop: 128x128x32 CTA tile, 3-stage cp.async, hand-rolled ldmatrix+mma.
// arow/brow: per-thread global srcs pre-offset to this thread's chunk.
template <int NSTG, int LDB>
__device__ __forceinline__ void gemm_core(const __half* arow, const __half* brow,
                                          uint32_t smb, int tid,
                                          float (&acc)[4][4][4]) {
    const int lane = tid & 31;
    const int wid  = tid >> 5;
    const int wm   = wid >> 2;   // 0..1 (64-row slab)
    const int wn   = wid & 3;    // 0..3 (32-col slab)

    // cp.async destination addresses (stage-relative, bytes)
    const uint32_t a_dst = (uint32_t)(((tid >> 1) * ASTR + (tid & 1) * 16) * 2);
    const uint32_t b_dst = (uint32_t)(A_BY + ((tid >> 3) * BSTR + (tid & 7) * 16) * 2);

    auto load_stage = [&](int s) {
        uint32_t base = smb + (uint32_t)((s % PIPE) * ST_BY);
        const __half* as = arow + s * BK;
        CP_ASYNC16(base + a_dst,      as);
        CP_ASYNC16(base + a_dst + 16, as + 8);
        const __half* bs = brow + (size_t)s * (BK * LDB);
        CP_ASYNC16(base + b_dst,      bs);
        CP_ASYNC16(base + b_dst + 16, bs + 8);
    };

    // ldmatrix source offsets (stage-relative, bytes)
    uint32_t aoff[4], boff[2];
#pragma unroll
    for (int mi = 0; mi < 4; mi++)
        aoff[mi] = (uint32_t)(((wm * 64 + mi * 16 + (lane & 15)) * ASTR + (lane >> 4) * 8) * 2);
#pragma unroll
    for (int j = 0; j < 2; j++)
        boff[j] = (uint32_t)(A_BY + ((lane & 15) * BSTR + wn * 32 + j * 16 + (lane >> 4) * 8) * 2);

#pragma unroll
    for (int mi = 0; mi < 4; mi++)
#pragma unroll
        for (int nj = 0; nj < 4; nj++)
#pragma unroll
            for (int q = 0; q < 4; q++) acc[mi][nj][q] = 0.f;

    load_stage(0); CP_COMMIT();
    load_stage(1); CP_COMMIT();

    for (int s = 0; s < NSTG; s++) {
        if (s + 1 < NSTG) asm volatile("cp.async.wait_group 1;" ::: "memory");
        else              asm volatile("cp.async.wait_group 0;" ::: "memory");
        __syncthreads();
        if (s + 2 < NSTG) { load_stage(s + 2); CP_COMMIT(); }

        uint32_t base = smb + (uint32_t)((s % PIPE) * ST_BY);

        uint32_t ar[2][4][4], br[2][2][4];
        // issue ALL ldmatrix for both k-steps up front (latency overlapped by mma)
#pragma unroll
        for (int ks = 0; ks < 2; ks++) {
#pragma unroll
            for (int mi = 0; mi < 4; mi++)
                LDSM_X4(ar[ks][mi][0], ar[ks][mi][1], ar[ks][mi][2], ar[ks][mi][3],
                        base + aoff[mi] + ks * 32);
#pragma unroll
            for (int j = 0; j < 2; j++)
                LDSM_X4T(br[ks][j][0], br[ks][j][1], br[ks][j][2], br[ks][j][3],
                         base + boff[j] + ks * (16 * BSTR * 2));
        }
#pragma unroll
        for (int ks = 0; ks < 2; ks++)
#pragma unroll
            for (int mi = 0; mi < 4; mi++)
#pragma unroll
                for (int j = 0; j < 2; j++) {
                    MMA16816(acc[mi][j * 2],     ar[ks][mi], br[ks][j][0], br[ks][j][1]);
                    MMA16816(acc[mi][j * 2 + 1], ar[ks][mi], br[ks][j][2], br[ks][j][3]);
                }
        // next iteration's wait_group + __syncthreads protects buffer reuse
    }
}

// ============================ GEMM1: H = gelu(X W1 + b1) ===================
__global__ __launch_bounds__(THREADS) void ffn1_tc(const float* __restrict__ b1) {
    int e = blockIdx.z;
    int cnt = g_cnt[e];
    int m0 = blockIdx.y * BM;
    if (m0 >= cnt) return;
    int n0 = blockIdx.x * BN;

    extern __shared__ __align__(16) char smem[];
    uint32_t smb = smem_u32(smem);
    int tid = threadIdx.x, lane = tid & 31, wid = tid >> 5;
    int wm = wid >> 2, wn = wid & 3;

    // A gather: clamp inactive rows to a valid slot (masked in epilogue)
    int gr = m0 + (tid >> 1);
    int tok = g_tok[e * CAP + (gr < cnt ? gr : cnt - 1)];
    const __half* arow = g_xh + (size_t)tok * DMODEL + (tid & 1) * 16;
    const __half* brow = g_W1h + ((size_t)e * DMODEL + (tid >> 3)) * FF + n0 + (tid & 7) * 16;

    float acc[4][4][4];
    gemm_core<DMODEL / BK, FF>(arow, brow, smb, tid, acc);

    // epilogue: bias + exact GELU -> fp16 H, straight from registers
    int gq = lane >> 2, lq = (lane & 3) * 2;
    int gnb = n0 + wn * 32 + lq;
    const float* bb = b1 + (size_t)e * FF + gnb;
    float2 bias[4];
#pragma unroll
    for (int j = 0; j < 4; j++) bias[j] = *(const float2*)(bb + j * 8);

#pragma unroll
    for (int mi = 0; mi < 4; mi++) {
        int r0g = m0 + wm * 64 + mi * 16 + gq;
#pragma unroll
        for (int h = 0; h < 2; h++) {          // row halves (+0, +8)
            int gm = r0g + h * 8;
            if (gm < cnt) {
                __half* hp = g_Hh + ((size_t)e * CAP + gm) * FF + gnb;
#pragma unroll
                for (int j = 0; j < 4; j++) {
                    float v0 = gelu_exact(acc[mi][j][h * 2]     + bias[j].x);
                    float v1 = gelu_exact(acc[mi][j][h * 2 + 1] + bias[j].y);
                    *(__half2*)(hp + j * 8) = __floats2half2_rn(v0, v1);
                }
            }
        }
    }
}

// ============================ GEMM2: Y = H W2 + b2 =========================
__global__ __launch_bounds__(THREADS) void ffn2_tc(const float* __restrict__ b2) {
    int e = blockIdx.z;
    int cnt = g_cnt[e];
    int m0 = blockIdx.y * BM;
    if (m0 >= cnt) return;
    int n0 = blockIdx.x * BN;

    extern __shared__ __align__(16) char smem[];
    uint32_t smb = smem_u32(smem);
    int tid = threadIdx.x, lane = tid & 31, wid = tid >> 5;
    int wm = wid >> 2, wn = wid & 3;

    const __half* arow = g_Hh + ((size_t)e * CAP + m0 + (tid >> 1)) * FF + (tid & 1) * 16;
    const __half* brow = g_W2h + ((size_t)e * FF + (tid >> 3)) * DMODEL + n0 + (tid & 7) * 16;

    float acc[4][4][4];
    gemm_core<FF / BK, DMODEL>(arow, brow, smb, tid, acc);

    int gq = lane >> 2, lq = (lane & 3) * 2;
    int gnb = n0 + wn * 32 + lq;
    const float* bb = b2 + (size_t)e * DMODEL + gnb;
    float2 bias[4];
#pragma unroll
    for (int j = 0; j < 4; j++) bias[j] = *(const float2*)(bb + j * 8);

#pragma unroll
    for (int mi = 0; mi < 4; mi++) {
        int r0g = m0 + wm * 64 + mi * 16 + gq;
#pragma unroll
        for (int h = 0; h < 2; h++) {
            int gm = r0g + h * 8;
            if (gm < cnt) {
                float* yp = g_Y + ((size_t)e * CAP + gm) * DMODEL + gnb;
#pragma unroll
                for (int j = 0; j < 4; j++) {
                    float2 v;
                    v.x = acc[mi][j][h * 2]     + bias[j].x;
                    v.y = acc[mi][j][h * 2 + 1] + bias[j].y;
                    *(float2*)(yp + j * 8) = v;
                }
            }
        }
    }
}

// ============================ combine + counter reset ======================
__global__ void combine_kernel(float* __restrict__ out) {
    int i = blockIdx.x * blockDim.x + threadIdx.x;   // over NTOK * DMODEL/4
    if (i < NTOK * (DMODEL / 4)) {
        int n  = i >> 8;            // DMODEL/4 == 256
        int c4 = i & 255;
        int   s1 = g_oslot[n * 2 + 0], s2 = g_oslot[n * 2 + 1];
        float g1 = g_ogate[n * 2 + 0], g2 = g_ogate[n * 2 + 1];
        float4 y1 = reinterpret_cast<const float4*>(g_Y + (size_t)s1 * DMODEL)[c4];
        float4 y2 = reinterpret_cast<const float4*>(g_Y + (size_t)s2 * DMODEL)[c4];
        float4 o;
        o.x = g1 * y1.x + g2 * y2.x;
        o.y = g1 * y1.y + g2 * y2.y;
        o.z = g1 * y1.z + g2 * y2.z;
        o.w = g1 * y1.w + g2 * y2.w;
        reinterpret_cast<float4*>(out)[i] = o;
    }
    if (blockIdx.x == 0 && threadIdx.x < NE) g_cnt[threadIdx.x] = 0;  // ready next call
}

// ============================ fp32 -> fp16 conversion ======================
__global__ void conv2(const float* __restrict__ s1, __half* __restrict__ d1, int n1,
                      const float* __restrict__ s2, __half* __restrict__ d2, int n2) {
    int i = blockIdx.x * blockDim.x + threadIdx.x;   // float4 units
    const float* s; __half* d; int k;
    if (i < n1)            { s = s1; d = d1; k = i; }
    else if (i < n1 + n2)  { s = s2; d = d2; k = i - n1; }
    else return;
    float4 v = reinterpret_cast<const float4*>(s)[k];
    __half2* dp = reinterpret_cast<__half2*>(d);
    dp[k * 2]     = __floats2half2_rn(v.x, v.y);
    dp[k * 2 + 1] = __floats2half2_rn(v.z, v.w);
}

// ============================ router =======================================
__global__ void router_kernel(const float* __restrict__ x, const float* __restrict__ Wr) {
    int warp = (blockIdx.x * blockDim.x + threadIdx.x) >> 5;
    int lane = threadIdx.x & 31;
    if (warp >= NTOK) return;

    const float* xr = x + (size_t)warp * DMODEL;
    float acc[NE];
#pragma unroll
    for (int e = 0; e < NE; e++) acc[e] = 0.f;
#pragma unroll 4
    for (int i = 0; i < DMODEL / 32; i++) {
        int d = i * 32 + lane;
        float xv = xr[d];
#pragma unroll
        for (int e = 0; e < NE; e++) acc[e] += xv * Wr[e * DMODEL + d];
    }
#pragma unroll
    for (int e = 0; e < NE; e++)
#pragma unroll
        for (int o = 16; o > 0; o >>= 1)
            acc[e] += __shfl_xor_sync(0xffffffffu, acc[e], o);

    if (lane == 0) {
        float m = acc[0];
#pragma unroll
        for (int e = 1; e < NE; e++) m = fmaxf(m, acc[e]);
        float p[NE];
#pragma unroll
        for (int e = 0; e < NE; e++) p[e] = expf(acc[e] - m);
        int i1 = 0;
#pragma unroll
        for (int e = 1; e < NE; e++) if (p[e] > p[i1]) i1 = e;
        int i2 = (i1 == 0) ? 1 : 0;
#pragma unroll
        for (int e = 0; e < NE; e++) {
            if (e == i1) continue;
            if (p[e] > p[i2]) i2 = e;
        }
        float g1 = p[i1], g2 = p[i2];
        float inv = 1.f / (g1 + g2);
        g1 *= inv; g2 *= inv;

        int pos1 = atomicAdd(&g_cnt[i1], 1);
        g_tok[i1 * CAP + pos1] = warp;
        g_oslot[warp * 2 + 0] = i1 * CAP + pos1;
        g_ogate[warp * 2 + 0] = g1;

        int pos2 = atomicAdd(&g_cnt[i2], 1);
        g_tok[i2 * CAP + pos2] = warp;
        g_oslot[warp * 2 + 1] = i2 * CAP + pos2;
        g_ogate[warp * 2 + 1] = g2;
    }
}

// ============================ launch =======================================
extern "C" void kernel_launch(void* const* d_in, const int* in_sizes, int n_in,
                              void* d_out, int out_size) {
    const float* x  = (const float*)d_in[0];
    const float* Wr = (const float*)d_in[1];
    const float* W1 = (const float*)d_in[2];
    const float* b1 = (const float*)d_in[3];
    const float* W2 = (const float*)d_in[4];
    const float* b2 = (const float*)d_in[5];
    float* out = (float*)d_out;

    cudaFuncSetAttribute(ffn1_tc, cudaFuncAttributeMaxDynamicSharedMemorySize, SMEM_BYTES);
    cudaFuncSetAttribute(ffn2_tc, cudaFuncAttributeMaxDynamicSharedMemorySize, SMEM_BYTES);

    __half *pXh = nullptr, *pW1h = nullptr, *pW2h = nullptr;
    cudaGetSymbolAddress((void**)&pXh,  g_xh);
    cudaGetSymbolAddress((void**)&pW1h, g_W1h);
    cudaGetSymbolAddress((void**)&pW2h, g_W2h);

    int nx4 = NTOK * DMODEL / 4;             // 2M
    int nw4 = NE * DMODEL * FF / 4;          // 4M

    router_kernel<<<(NTOK * 32) / 256, 256>>>(x, Wr);                     // 1
    conv2<<<(nx4 + nw4 + 255) / 256, 256>>>(x, pXh, nx4, W1, pW1h, nw4);  // 2
    conv2<<<(nw4 + 255) / 256, 256>>>(W2, pW2h, nw4, W2, pW2h, 0);        // 3
    ffn1_tc<<<dim3(FF / BN, CAP / BM, NE), THREADS, SMEM_BYTES>>>(b1);    // 4
    ffn2_tc<<<dim3(DMODEL / BN, CAP / BM, NE), THREADS, SMEM_BYTES>>>(b2);// 5
    combine_kernel<<<(NTOK * DMODEL / 4 + 255) / 256, 256>>>(out);        // 6
}